// round 3
// baseline (speedup 1.0000x reference)
#include <cuda_runtime.h>
#include <math.h>

#define NTOK 64
#define HEADS 8
#define DH 32
#define DEPTH 2
#define DMODEL 256
#define MLPD 1024
#define NWIN 1024          // 4 * 16 * 16
#define MROWS (NWIN*NTOK)  // 65536
#define LN_EPS 1e-5f
#define ATT_SCALE 0.17677669529663687f   // 32^-0.5
#define OUT_ELEMS 16777216               // 4*256*128*128

// ---------------- scratch (device globals; no allocation allowed) ----------
__device__ float g_gather[MROWS * DMODEL];          // windowed input, 64 MB
__device__ float g_t[MROWS * DMODEL];               // residual stream
__device__ float g_h[MROWS * DMODEL];               // LN output
__device__ float g_qkv[MROWS * 3 * DMODEL];         // 192 MB
__device__ float g_o[MROWS * DMODEL];               // attention output
__device__ float g_mlp[MROWS * MLPD];               // 256 MB
__device__ float g_add[DEPTH * HEADS * NTOK * NTOK];// bias + 0.01*pos table

// buffer ids: 0=g_gather 1=g_t 2=g_h 3=g_qkv 4=g_o 5=g_mlp
__device__ __forceinline__ float* buf(int id) {
    switch (id) {
        case 0: return g_gather;
        case 1: return g_t;
        case 2: return g_h;
        case 3: return g_qkv;
        case 4: return g_o;
        default: return g_mlp;
    }
}

// ---------------- window gather: x[B,C,H,W] -> g_gather[win*64+tok, C] -----
__global__ void gather_kernel(const float* __restrict__ x) {
    int win = blockIdx.x;                 // ((b*16+wh)*16+ww)
    int b  = win >> 8;
    int wh = (win >> 4) & 15;
    int ww = win & 15;
    const float* xb = x + (size_t)b * 256 * 128 * 128;
    float* dst = g_gather + (size_t)win * NTOK * DMODEL;
    for (int idx = threadIdx.x; idx < NTOK * DMODEL; idx += blockDim.x) {
        int tok = idx >> 8;
        int c   = idx & 255;
        int y = tok >> 3, xx = tok & 7;
        int hh = wh * 8 + y, ww2 = ww * 8 + xx;
        dst[idx] = xb[((size_t)c * 128 + hh) * 128 + ww2];
    }
}

// ---------------- generic 64x64 tiled SGEMM with epilogue options ----------
// A = buf(aid), C = buf(cid), residual (if RESID) = g_t. B/bias from gmem.
template<bool BIASF, bool RELU, bool RESID>
__global__ void gemm64(int aid, const float* __restrict__ B,
                       const float* __restrict__ bias,
                       int cid, int M, int N, int K) {
    const float* __restrict__ A = buf(aid);
    float* __restrict__ C = buf(cid);
    __shared__ float As[64][17];
    __shared__ float Bs[16][64];
    int tid = threadIdx.x;
    int m0 = blockIdx.y * 64;
    int n0 = blockIdx.x * 64;
    int arow = tid >> 2, acol = (tid & 3) * 4;
    int brow = tid >> 4, bcol = (tid & 15) * 4;
    int ty = tid >> 4, tx = tid & 15;
    float acc[4][4] = {};
    for (int k0 = 0; k0 < K; k0 += 16) {
        float4 av = *(const float4*)(A + (size_t)(m0 + arow) * K + k0 + acol);
        As[arow][acol + 0] = av.x; As[arow][acol + 1] = av.y;
        As[arow][acol + 2] = av.z; As[arow][acol + 3] = av.w;
        *(float4*)(&Bs[brow][bcol]) =
            *(const float4*)(B + (size_t)(k0 + brow) * N + n0 + bcol);
        __syncthreads();
        #pragma unroll
        for (int k = 0; k < 16; k++) {
            float a[4], bb[4];
            #pragma unroll
            for (int i = 0; i < 4; i++) a[i] = As[ty * 4 + i][k];
            #pragma unroll
            for (int j = 0; j < 4; j++) bb[j] = Bs[k][tx * 4 + j];
            #pragma unroll
            for (int i = 0; i < 4; i++)
                #pragma unroll
                for (int j = 0; j < 4; j++)
                    acc[i][j] += a[i] * bb[j];
        }
        __syncthreads();
    }
    #pragma unroll
    for (int i = 0; i < 4; i++) {
        int m = m0 + ty * 4 + i;
        float* crow = C + (size_t)m * N + n0;
        const float* rrow = RESID ? (g_t + (size_t)m * N + n0) : (const float*)0;
        #pragma unroll
        for (int j = 0; j < 4; j++) {
            int n = tx * 4 + j;
            float v = acc[i][j];
            if (BIASF) v += bias[n0 + n];
            if (RELU)  v = fmaxf(v, 0.f);
            if (RESID) v += rrow[n];
            crow[n] = v;
        }
    }
}

// ---------------- LayerNorm over last dim (256): g_t -> g_h ----------------
__global__ void ln_kernel(const float* __restrict__ g, const float* __restrict__ b) {
    int row  = blockIdx.x * 8 + (threadIdx.x >> 5);
    int lane = threadIdx.x & 31;
    const float* p = g_t + (size_t)row * DMODEL;
    float v[8];
    float s = 0.f;
    #pragma unroll
    for (int i = 0; i < 8; i++) { v[i] = p[lane + i * 32]; s += v[i]; }
    #pragma unroll
    for (int o = 16; o; o >>= 1) s += __shfl_xor_sync(0xffffffffu, s, o);
    float mean = s * (1.f / 256.f);
    float vs = 0.f;
    #pragma unroll
    for (int i = 0; i < 8; i++) { float d = v[i] - mean; vs += d * d; }
    #pragma unroll
    for (int o = 16; o; o >>= 1) vs += __shfl_xor_sync(0xffffffffu, vs, o);
    float r = rsqrtf(vs * (1.f / 256.f) + LN_EPS);
    float* q = g_h + (size_t)row * DMODEL;
    #pragma unroll
    for (int i = 0; i < 8; i++) {
        int col = lane + i * 32;
        q[col] = (v[i] - mean) * r * g[col] + b[col];
    }
}

// ---------------- precompute bias + 0.01 * gaussian decay ------------------
__global__ void addmat_kernel(const float* __restrict__ bias_table,
                              const float* __restrict__ headsita) {
    int idx = blockIdx.x * blockDim.x + threadIdx.x;  // 65536 total
    if (idx >= DEPTH * HEADS * NTOK * NTOK) return;
    int j = idx & 63, i = (idx >> 6) & 63, head = (idx >> 12) & 7, l = idx >> 15;
    int yi = i >> 3, xi = i & 7, yj = j >> 3, xj = j & 7;
    int dy = yi - yj, dx = xi - xj;
    int tbl = (dy + 7) * 15 + (dx + 7);
    float bias = bias_table[(l * 225 + tbl) * 8 + head];
    float sita = headsita[l * 8 + head];
    float factor = 1.0f / (2.0f * sita * sita + 1e-10f);
    float fy = (float)dy * 0.125f, fx = (float)dx * 0.125f;
    float dis = fy * fy + fx * fx;
    g_add[idx] = bias + 0.01f * expf(-factor * dis);
}

// ---------------- fused windowed attention per (window, head) --------------
// reads g_qkv, writes g_o and the attns side output
__global__ void attn_kernel(float* __restrict__ attns_out, int layer) {
    int win  = blockIdx.x >> 3;
    int head = blockIdx.x & 7;
    __shared__ float qs[64][33], ks[64][33], vs_[64][33];
    __shared__ float ds[64][64];
    int tid = threadIdx.x;
    int warp = tid >> 5, lane = tid & 31;
    const float* base = g_qkv + (size_t)win * 64 * 768 + head * 32;
    for (int tok = warp; tok < 64; tok += 8) {
        qs[tok][lane]  = base[tok * 768 + lane];
        ks[tok][lane]  = base[tok * 768 + 256 + lane];
        vs_[tok][lane] = base[tok * 768 + 512 + lane];
    }
    __syncthreads();
    for (int p = tid; p < 4096; p += 256) {
        int i = p >> 6, j = p & 63;
        float acc = 0.f;
        #pragma unroll
        for (int d = 0; d < 32; d++) acc += qs[i][d] * ks[j][d];
        ds[i][j] = acc * ATT_SCALE;
    }
    __syncthreads();
    const float* addb = g_add + ((size_t)(layer * 8 + head)) * 4096;
    float* a_out = attns_out + (((size_t)layer * NWIN + win) * 8 + head) * 4096;
    for (int i = warp; i < 64; i += 8) {
        float x0 = ds[i][lane], x1 = ds[i][lane + 32];
        // softmax of dots0 (attns side output)
        float m = fmaxf(x0, x1);
        #pragma unroll
        for (int sh = 16; sh; sh >>= 1) m = fmaxf(m, __shfl_xor_sync(0xffffffffu, m, sh));
        float e0 = __expf(x0 - m), e1 = __expf(x1 - m);
        float s = e0 + e1;
        #pragma unroll
        for (int sh = 16; sh; sh >>= 1) s += __shfl_xor_sync(0xffffffffu, s, sh);
        float inv = 1.f / s;
        a_out[i * 64 + lane]      = e0 * inv;
        a_out[i * 64 + lane + 32] = e1 * inv;
        // biased softmax (used for context)
        float y0 = x0 + addb[i * 64 + lane];
        float y1 = x1 + addb[i * 64 + lane + 32];
        float m2 = fmaxf(y0, y1);
        #pragma unroll
        for (int sh = 16; sh; sh >>= 1) m2 = fmaxf(m2, __shfl_xor_sync(0xffffffffu, m2, sh));
        float f0 = __expf(y0 - m2), f1 = __expf(y1 - m2);
        float s2 = f0 + f1;
        #pragma unroll
        for (int sh = 16; sh; sh >>= 1) s2 += __shfl_xor_sync(0xffffffffu, s2, sh);
        float inv2 = 1.f / s2;
        ds[i][lane]      = f0 * inv2;
        ds[i][lane + 32] = f1 * inv2;
    }
    __syncthreads();
    float* ob = g_o + (size_t)win * 64 * 256 + head * 32;
    for (int p = tid; p < 2048; p += 256) {
        int i = p >> 5, d = p & 31;
        float acc = 0.f;
        #pragma unroll
        for (int j = 0; j < 64; j++) acc += ds[i][j] * vs_[j][d];
        ob[i * 256 + d] = acc;
    }
}

// ---------------- window reverse: g_t -> out[B,D,H,W] ----------------------
__global__ void unpermute_kernel(float* __restrict__ out) {
    int idx = blockIdx.x * 256 + threadIdx.x;   // 16777216 total
    int w = idx & 127, h2 = (idx >> 7) & 127, d = (idx >> 14) & 255, b = idx >> 22;
    int win = (b * 16 + (h2 >> 3)) * 16 + (w >> 3);
    int tok = (h2 & 7) * 8 + (w & 7);
    out[idx] = g_t[((size_t)win * 64 + tok) * 256 + d];
}

// ---------------------------------------------------------------------------
extern "C" void kernel_launch(void* const* d_in, const int* in_sizes, int n_in,
                              void* d_out, int out_size) {
    const float* x          = (const float*)d_in[0];
    const float* W_patch    = (const float*)d_in[1];
    const float* b_patch    = (const float*)d_in[2];
    const float* ln1_g      = (const float*)d_in[3];
    const float* ln1_b      = (const float*)d_in[4];
    const float* Wqkv       = (const float*)d_in[5];
    const float* headsita   = (const float*)d_in[6];
    const float* bias_table = (const float*)d_in[7];
    const float* Wout       = (const float*)d_in[8];
    const float* bout       = (const float*)d_in[9];
    const float* ln2_g      = (const float*)d_in[10];
    const float* ln2_b      = (const float*)d_in[11];
    const float* W1         = (const float*)d_in[12];
    const float* b1         = (const float*)d_in[13];
    const float* W2         = (const float*)d_in[14];
    const float* b2         = (const float*)d_in[15];

    float* out   = (float*)d_out;
    float* attns = out + OUT_ELEMS;

    // bias + gaussian table
    addmat_kernel<<<256, 256>>>(bias_table, headsita);
    // window partition
    gather_kernel<<<NWIN, 256>>>(x);
    // patch embed: g_t = g_gather @ W_patch + b_patch
    gemm64<true, false, false><<<dim3(DMODEL / 64, MROWS / 64), 256>>>(
        0, W_patch, b_patch, 1, MROWS, DMODEL, DMODEL);

    for (int l = 0; l < DEPTH; l++) {
        // LN1: g_t -> g_h
        ln_kernel<<<MROWS / 8, 256>>>(ln1_g + l * DMODEL, ln1_b + l * DMODEL);
        // g_qkv = g_h @ Wqkv[l]
        gemm64<false, false, false><<<dim3(768 / 64, MROWS / 64), 256>>>(
            2, Wqkv + (size_t)l * DMODEL * 768, (const float*)0, 3,
            MROWS, 768, DMODEL);
        // attention (also writes softmax(dots0) to attns output)
        attn_kernel<<<NWIN * HEADS, 256>>>(attns, l);
        // g_t = g_o @ Wout[l] + bout[l] + g_t
        gemm64<true, false, true><<<dim3(DMODEL / 64, MROWS / 64), 256>>>(
            4, Wout + (size_t)l * DMODEL * DMODEL, bout + l * DMODEL, 1,
            MROWS, DMODEL, DMODEL);
        // LN2: g_t -> g_h
        ln_kernel<<<MROWS / 8, 256>>>(ln2_g + l * DMODEL, ln2_b + l * DMODEL);
        // g_mlp = relu(g_h @ W1[l] + b1[l])
        gemm64<true, true, false><<<dim3(MLPD / 64, MROWS / 64), 256>>>(
            2, W1 + (size_t)l * DMODEL * MLPD, b1 + l * MLPD, 5,
            MROWS, MLPD, DMODEL);
        // g_t = g_mlp @ W2[l] + b2[l] + g_t
        gemm64<true, false, true><<<dim3(DMODEL / 64, MROWS / 64), 256>>>(
            5, W2 + (size_t)l * MLPD * DMODEL, b2 + l * DMODEL, 1,
            MROWS, DMODEL, MLPD);
    }

    // window reverse into d_out
    unpermute_kernel<<<OUT_ELEMS / 256, 256>>>(out);
}

// round 7
// speedup vs baseline: 1.6192x; 1.6192x over previous
#include <cuda_runtime.h>
#include <mma.h>
#include <math.h>

using namespace nvcuda;

#define NTOK 64
#define HEADS 8
#define DH 32
#define DEPTH 2
#define DMODEL 256
#define MLPD 1024
#define NWIN 1024          // 4 * 16 * 16
#define MROWS (NWIN*NTOK)  // 65536
#define LN_EPS 1e-5f
#define ATT_SCALE 0.17677669529663687f   // 32^-0.5
#define OUT_ELEMS 16777216               // 4*256*128*128

// ---------------- scratch (device globals; no allocation allowed) ----------
__device__ float g_gather[MROWS * DMODEL];
__device__ float g_t[MROWS * DMODEL];
__device__ float g_h[MROWS * DMODEL];
__device__ float g_qkv[MROWS * 3 * DMODEL];
__device__ float g_o[MROWS * DMODEL];
__device__ float g_mlp[MROWS * MLPD];
__device__ float g_add[DEPTH * HEADS * NTOK * NTOK];

// buffer ids: 0=g_gather 1=g_t 2=g_h 3=g_qkv 4=g_o 5=g_mlp
__device__ __forceinline__ float* buf(int id) {
    switch (id) {
        case 0: return g_gather;
        case 1: return g_t;
        case 2: return g_h;
        case 3: return g_qkv;
        case 4: return g_o;
        default: return g_mlp;
    }
}

// ---------------- window gather ----------------
__global__ void gather_kernel(const float* __restrict__ x) {
    int win = blockIdx.x;
    int b  = win >> 8;
    int wh = (win >> 4) & 15;
    int ww = win & 15;
    const float* xb = x + (size_t)b * 256 * 128 * 128;
    float* dst = g_gather + (size_t)win * NTOK * DMODEL;
    for (int idx = threadIdx.x; idx < NTOK * DMODEL; idx += blockDim.x) {
        int tok = idx >> 8;
        int c   = idx & 255;
        int y = tok >> 3, xx = tok & 7;
        int hh = wh * 8 + y, ww2 = ww * 8 + xx;
        dst[idx] = xb[((size_t)c * 128 + hh) * 128 + ww2];
    }
}

// ---------------- tf32 tensor-core GEMM, 128x64 block tile -----------------
// A = buf(aid) [M,K] row-major, B [K,N] row-major, C = buf(cid).
// 256 threads = 8 warps: warp grid 4x2, warp tile 32x32 (2x2 wmma 16x16).
template<bool BIASF, bool RELU, bool RESID>
__global__ void __launch_bounds__(256)
gemm_tc(int aid, const float* __restrict__ B, const float* __restrict__ bias,
        int cid, int M, int N, int K) {
    const float* __restrict__ A = buf(aid);
    float* __restrict__ C = buf(cid);

    // mainloop: As(128x36)=4608 | Bs(32x68)=2176  (6784 floats)
    // epilogue staging: 8 warps x 32x36 = 9216 floats (reuses same smem)
    __shared__ float smem_all[9216];
    float* As = smem_all;                      // As[m*36+k]
    float* Bs = smem_all + 128 * 36;           // Bs[k*68+n]

    int tid = threadIdx.x;
    int w   = tid >> 5;
    int lane = tid & 31;
    int wr = w >> 1, wc = w & 1;               // warp grid 4x2
    int m0 = blockIdx.y * 128;
    int n0 = blockIdx.x * 64;

    wmma::fragment<wmma::accumulator, 16, 16, 8, float> acc[2][2];
    #pragma unroll
    for (int i = 0; i < 2; i++)
        #pragma unroll
        for (int j = 0; j < 2; j++)
            wmma::fill_fragment(acc[i][j], 0.0f);

    int a_m = tid >> 3;                        // 0..31
    int a_k = (tid & 7) * 4;
    int b_k = tid >> 4;                        // 0..15
    int b_n = (tid & 15) * 4;

    for (int k0 = 0; k0 < K; k0 += 32) {
        // load A tile 128x32
        #pragma unroll
        for (int ch = 0; ch < 4; ch++) {
            int m = a_m + ch * 32;
            float4 v = *(const float4*)(A + (size_t)(m0 + m) * K + k0 + a_k);
            float* p = As + m * 36 + a_k;
            p[0] = wmma::__float_to_tf32(v.x);
            p[1] = wmma::__float_to_tf32(v.y);
            p[2] = wmma::__float_to_tf32(v.z);
            p[3] = wmma::__float_to_tf32(v.w);
        }
        // load B tile 32x64
        #pragma unroll
        for (int ch = 0; ch < 2; ch++) {
            int k = b_k + ch * 16;
            float4 v = *(const float4*)(B + (size_t)(k0 + k) * N + n0 + b_n);
            float* p = Bs + k * 68 + b_n;
            p[0] = wmma::__float_to_tf32(v.x);
            p[1] = wmma::__float_to_tf32(v.y);
            p[2] = wmma::__float_to_tf32(v.z);
            p[3] = wmma::__float_to_tf32(v.w);
        }
        __syncthreads();
        #pragma unroll
        for (int ks = 0; ks < 4; ks++) {
            wmma::fragment<wmma::matrix_a, 16, 16, 8, wmma::precision::tf32, wmma::row_major> af[2];
            wmma::fragment<wmma::matrix_b, 16, 16, 8, wmma::precision::tf32, wmma::row_major> bf[2];
            #pragma unroll
            for (int i = 0; i < 2; i++)
                wmma::load_matrix_sync(af[i], As + (wr * 32 + i * 16) * 36 + ks * 8, 36);
            #pragma unroll
            for (int j = 0; j < 2; j++)
                wmma::load_matrix_sync(bf[j], Bs + (ks * 8) * 68 + wc * 32 + j * 16, 68);
            #pragma unroll
            for (int i = 0; i < 2; i++)
                #pragma unroll
                for (int j = 0; j < 2; j++)
                    wmma::mma_sync(acc[i][j], af[i], bf[j], acc[i][j]);
        }
        __syncthreads();
    }

    // stage accumulators through smem (per-warp 32x36, ldm=36: multiple of 4
    // elements as required for fp32 store_matrix_sync), then coalesced epilogue
    float* cw = smem_all + w * 1152;
    #pragma unroll
    for (int i = 0; i < 2; i++)
        #pragma unroll
        for (int j = 0; j < 2; j++)
            wmma::store_matrix_sync(cw + (i * 16) * 36 + j * 16, acc[i][j], 36, wmma::mem_row_major);
    __syncwarp();

    int ncol = n0 + wc * 32 + lane;
    float bv = BIASF ? bias[ncol] : 0.0f;
    #pragma unroll 4
    for (int r = 0; r < 32; r++) {
        int m = m0 + wr * 32 + r;
        float v = cw[r * 36 + lane];
        if (BIASF) v += bv;
        if (RELU)  v = fmaxf(v, 0.f);
        if (RESID) v += g_t[(size_t)m * N + ncol];
        C[(size_t)m * N + ncol] = v;
    }
}

// ---------------- LayerNorm over last dim (256): g_t -> g_h ----------------
__global__ void ln_kernel(const float* __restrict__ g, const float* __restrict__ b) {
    int row  = blockIdx.x * 8 + (threadIdx.x >> 5);
    int lane = threadIdx.x & 31;
    const float* p = g_t + (size_t)row * DMODEL;
    float v[8];
    float s = 0.f;
    #pragma unroll
    for (int i = 0; i < 8; i++) { v[i] = p[lane + i * 32]; s += v[i]; }
    #pragma unroll
    for (int o = 16; o; o >>= 1) s += __shfl_xor_sync(0xffffffffu, s, o);
    float mean = s * (1.f / 256.f);
    float vs = 0.f;
    #pragma unroll
    for (int i = 0; i < 8; i++) { float d = v[i] - mean; vs += d * d; }
    #pragma unroll
    for (int o = 16; o; o >>= 1) vs += __shfl_xor_sync(0xffffffffu, vs, o);
    float r = rsqrtf(vs * (1.f / 256.f) + LN_EPS);
    float* q = g_h + (size_t)row * DMODEL;
    #pragma unroll
    for (int i = 0; i < 8; i++) {
        int col = lane + i * 32;
        q[col] = (v[i] - mean) * r * g[col] + b[col];
    }
}

// ---------------- precompute bias + 0.01 * gaussian decay ------------------
__global__ void addmat_kernel(const float* __restrict__ bias_table,
                              const float* __restrict__ headsita) {
    int idx = blockIdx.x * blockDim.x + threadIdx.x;
    if (idx >= DEPTH * HEADS * NTOK * NTOK) return;
    int j = idx & 63, i = (idx >> 6) & 63, head = (idx >> 12) & 7, l = idx >> 15;
    int yi = i >> 3, xi = i & 7, yj = j >> 3, xj = j & 7;
    int dy = yi - yj, dx = xi - xj;
    int tbl = (dy + 7) * 15 + (dx + 7);
    float bias = bias_table[(l * 225 + tbl) * 8 + head];
    float sita = headsita[l * 8 + head];
    float factor = 1.0f / (2.0f * sita * sita + 1e-10f);
    float fy = (float)dy * 0.125f, fx = (float)dx * 0.125f;
    float dis = fy * fy + fx * fx;
    g_add[idx] = bias + 0.01f * expf(-factor * dis);
}

// ---------------- fused windowed attention per (window, head) --------------
__global__ void attn_kernel(float* __restrict__ attns_out, int layer) {
    int win  = blockIdx.x >> 3;
    int head = blockIdx.x & 7;
    __shared__ float qs[64][33], ks[64][33], vs_[64][33];
    __shared__ float ds[64][65];
    int tid = threadIdx.x;
    int warp = tid >> 5, lane = tid & 31;
    const float* base = g_qkv + (size_t)win * 64 * 768 + head * 32;
    for (int tok = warp; tok < 64; tok += 8) {
        qs[tok][lane]  = base[tok * 768 + lane];
        ks[tok][lane]  = base[tok * 768 + 256 + lane];
        vs_[tok][lane] = base[tok * 768 + 512 + lane];
    }
    __syncthreads();
    // QK^T with 4x4 register tiling
    {
        int ty = tid >> 4, tx = tid & 15;
        int i0 = ty * 4, j0 = tx * 4;
        float acc[4][4] = {};
        #pragma unroll 8
        for (int d = 0; d < 32; d++) {
            float qv[4], kv[4];
            #pragma unroll
            for (int r = 0; r < 4; r++) qv[r] = qs[i0 + r][d];
            #pragma unroll
            for (int c = 0; c < 4; c++) kv[c] = ks[j0 + c][d];
            #pragma unroll
            for (int r = 0; r < 4; r++)
                #pragma unroll
                for (int c = 0; c < 4; c++)
                    acc[r][c] += qv[r] * kv[c];
        }
        #pragma unroll
        for (int r = 0; r < 4; r++)
            #pragma unroll
            for (int c = 0; c < 4; c++)
                ds[i0 + r][j0 + c] = acc[r][c] * ATT_SCALE;
    }
    __syncthreads();
    const float* addb = g_add + ((size_t)(layer * 8 + head)) * 4096;
    float* a_out = attns_out + (((size_t)layer * NWIN + win) * 8 + head) * 4096;
    for (int i = warp; i < 64; i += 8) {
        float x0 = ds[i][lane], x1 = ds[i][lane + 32];
        float m = fmaxf(x0, x1);
        #pragma unroll
        for (int sh = 16; sh; sh >>= 1) m = fmaxf(m, __shfl_xor_sync(0xffffffffu, m, sh));
        float e0 = __expf(x0 - m), e1 = __expf(x1 - m);
        float s = e0 + e1;
        #pragma unroll
        for (int sh = 16; sh; sh >>= 1) s += __shfl_xor_sync(0xffffffffu, s, sh);
        float inv = 1.f / s;
        a_out[i * 64 + lane]      = e0 * inv;
        a_out[i * 64 + lane + 32] = e1 * inv;
        float y0 = x0 + addb[i * 64 + lane];
        float y1 = x1 + addb[i * 64 + lane + 32];
        float m2 = fmaxf(y0, y1);
        #pragma unroll
        for (int sh = 16; sh; sh >>= 1) m2 = fmaxf(m2, __shfl_xor_sync(0xffffffffu, m2, sh));
        float f0 = __expf(y0 - m2), f1 = __expf(y1 - m2);
        float s2 = f0 + f1;
        #pragma unroll
        for (int sh = 16; sh; sh >>= 1) s2 += __shfl_xor_sync(0xffffffffu, s2, sh);
        float inv2 = 1.f / s2;
        ds[i][lane]      = f0 * inv2;
        ds[i][lane + 32] = f1 * inv2;
    }
    __syncthreads();
    // P @ V with 4x2 register tiling
    {
        int ty = tid >> 4, tx = tid & 15;
        int i0 = ty * 4, d0 = tx * 2;
        float acc[4][2] = {};
        #pragma unroll 8
        for (int j = 0; j < 64; j++) {
            float dv[4], vv[2];
            #pragma unroll
            for (int r = 0; r < 4; r++) dv[r] = ds[i0 + r][j];
            #pragma unroll
            for (int c = 0; c < 2; c++) vv[c] = vs_[j][d0 + c];
            #pragma unroll
            for (int r = 0; r < 4; r++)
                #pragma unroll
                for (int c = 0; c < 2; c++)
                    acc[r][c] += dv[r] * vv[c];
        }
        float* ob = g_o + (size_t)win * 64 * 256 + head * 32;
        #pragma unroll
        for (int r = 0; r < 4; r++)
            #pragma unroll
            for (int c = 0; c < 2; c++)
                ob[(i0 + r) * 256 + d0 + c] = acc[r][c];
    }
}

// ---------------- window reverse: g_t -> out[B,D,H,W] ----------------------
__global__ void unpermute_kernel(float* __restrict__ out) {
    int idx = blockIdx.x * 256 + threadIdx.x;
    int w = idx & 127, h2 = (idx >> 7) & 127, d = (idx >> 14) & 255, b = idx >> 22;
    int win = (b * 16 + (h2 >> 3)) * 16 + (w >> 3);
    int tok = (h2 & 7) * 8 + (w & 7);
    out[idx] = g_t[((size_t)win * 64 + tok) * 256 + d];
}

// ---------------------------------------------------------------------------
extern "C" void kernel_launch(void* const* d_in, const int* in_sizes, int n_in,
                              void* d_out, int out_size) {
    const float* x          = (const float*)d_in[0];
    const float* W_patch    = (const float*)d_in[1];
    const float* b_patch    = (const float*)d_in[2];
    const float* ln1_g      = (const float*)d_in[3];
    const float* ln1_b      = (const float*)d_in[4];
    const float* Wqkv       = (const float*)d_in[5];
    const float* headsita   = (const float*)d_in[6];
    const float* bias_table = (const float*)d_in[7];
    const float* Wout       = (const float*)d_in[8];
    const float* bout       = (const float*)d_in[9];
    const float* ln2_g      = (const float*)d_in[10];
    const float* ln2_b      = (const float*)d_in[11];
    const float* W1         = (const float*)d_in[12];
    const float* b1         = (const float*)d_in[13];
    const float* W2         = (const float*)d_in[14];
    const float* b2         = (const float*)d_in[15];

    float* out   = (float*)d_out;
    float* attns = out + OUT_ELEMS;

    addmat_kernel<<<256, 256>>>(bias_table, headsita);
    gather_kernel<<<NWIN, 256>>>(x);
    // patch embed: g_t = g_gather @ W_patch + b_patch
    gemm_tc<true, false, false><<<dim3(DMODEL / 64, MROWS / 128), 256>>>(
        0, W_patch, b_patch, 1, MROWS, DMODEL, DMODEL);

    for (int l = 0; l < DEPTH; l++) {
        ln_kernel<<<MROWS / 8, 256>>>(ln1_g + l * DMODEL, ln1_b + l * DMODEL);
        // g_qkv = g_h @ Wqkv[l]
        gemm_tc<false, false, false><<<dim3(768 / 64, MROWS / 128), 256>>>(
            2, Wqkv + (size_t)l * DMODEL * 768, (const float*)0, 3,
            MROWS, 768, DMODEL);
        attn_kernel<<<NWIN * HEADS, 256>>>(attns, l);
        // g_t = g_o @ Wout[l] + bout[l] + g_t
        gemm_tc<true, false, true><<<dim3(DMODEL / 64, MROWS / 128), 256>>>(
            4, Wout + (size_t)l * DMODEL * DMODEL, bout + l * DMODEL, 1,
            MROWS, DMODEL, DMODEL);
        ln_kernel<<<MROWS / 8, 256>>>(ln2_g + l * DMODEL, ln2_b + l * DMODEL);
        // g_mlp = relu(g_h @ W1[l] + b1[l])
        gemm_tc<true, true, false><<<dim3(MLPD / 64, MROWS / 128), 256>>>(
            2, W1 + (size_t)l * DMODEL * MLPD, b1 + l * MLPD, 5,
            MROWS, MLPD, DMODEL);
        // g_t = g_mlp @ W2[l] + b2[l] + g_t
        gemm_tc<true, false, true><<<dim3(DMODEL / 64, MROWS / 128), 256>>>(
            5, W2 + (size_t)l * MLPD * DMODEL, b2 + l * DMODEL, 1,
            MROWS, DMODEL, MLPD);
    }

    unpermute_kernel<<<OUT_ELEMS / 256, 256>>>(out);
}